// round 16
// baseline (speedup 1.0000x reference)
#include <cuda_runtime.h>
#include <cuda_bf16.h>
#include <cuda_fp16.h>
#include <cstdint>

// ---------------------------------------------------------------------------
// SAGESparseLayer:
//   mean[n] = (1/max(deg(n),1)) * sum_{e: dst[e]==n} feature[src[e]] * rw[e]
//   out[n]  = [feature[n], mean[n]] @ W + b
//
// R16 (= R15 resubmit after infra failure): launches = [mega, gemm].
//  mega: 4 gbars; hist+convert | scan | offsets | scatter+zero | agg.
//  gemm: flat cross-strip cp.async pipeline — 2-kstep chunks, 3 rotating
//        warp-private buffers, issue cursor 3 chunks ahead of compute,
//        no strip-boundary drain. W col-half per CTA. 2 CTAs/SM.
// ---------------------------------------------------------------------------

#define D_FEAT    128
#define OUT_DIM   128
#define MAX_NODES 131072
#define MAX_EDGES (1 << 20)
#define MAX_CHUNKS 256
#define MEGA_THREADS 1024

static __device__ __align__(16) uint2 g_feat16[(size_t)MAX_NODES * 32];  // fp16 feat
static __device__ __align__(16) uint2 g_mean16[(size_t)MAX_NODES * 32];  // fp16 mean
static __device__ int  g_cnt[MAX_NODES];          // ZERO at every launch entry
static __device__ int  g_rowstart[MAX_NODES + 1];
static __device__ int  g_cursor[MAX_NODES];
static __device__ int  g_chunksum[MAX_CHUNKS];
static __device__ __align__(8) int2 g_edges[MAX_EDGES];

// software grid barrier state (replay-safe: even #barriers per launch)
static __device__ int g_bar_cnt;
static __device__ volatile int g_bar_sense;

__device__ __forceinline__ void gbar(int grid, int* lsense) {
    __syncthreads();
    if (threadIdx.x == 0) {
        int s = *lsense ^ 1;
        *lsense = s;
        __threadfence();
        if (atomicAdd(&g_bar_cnt, 1) == grid - 1) {
            g_bar_cnt = 0;
            __threadfence();
            g_bar_sense = s;
        } else {
            while (g_bar_sense != s) __nanosleep(64);
        }
        __threadfence();
    }
    __syncthreads();
}

// ---------------------------------------------------------------------------
// agg helper: accumulate one edge's 8 features (fp16x2 -> f32 fma)
// ---------------------------------------------------------------------------
__device__ __forceinline__ void agg_edge(float* a, uint4 u, float w) {
    float2 p;
    p = __half22float2(*reinterpret_cast<__half2*>(&u.x));
    a[0] = fmaf(p.x, w, a[0]); a[1] = fmaf(p.y, w, a[1]);
    p = __half22float2(*reinterpret_cast<__half2*>(&u.y));
    a[2] = fmaf(p.x, w, a[2]); a[3] = fmaf(p.y, w, a[3]);
    p = __half22float2(*reinterpret_cast<__half2*>(&u.z));
    a[4] = fmaf(p.x, w, a[4]); a[5] = fmaf(p.y, w, a[5]);
    p = __half22float2(*reinterpret_cast<__half2*>(&u.w));
    a[6] = fmaf(p.x, w, a[6]); a[7] = fmaf(p.y, w, a[7]);
}

// ---------------------------------------------------------------------------
// mega kernel: hist+convert | chunk scan | offsets | scatter+zero | agg
// ---------------------------------------------------------------------------
__global__ void __launch_bounds__(MEGA_THREADS, 1) mega_kernel(
    const float* __restrict__ feat,
    const float* __restrict__ rw,
    const int*   __restrict__ rel_idx,
    int N, int E, int grid)
{
    __shared__ int ws[32];
    __shared__ int chunkoff[MAX_CHUNKS];
    const int tid = threadIdx.x;
    const int cta = blockIdx.x;
    const int gthreads = grid * MEGA_THREADS;
    const int gtid = cta * MEGA_THREADS + tid;
    const int nchunks = (N + MEGA_THREADS - 1) / MEGA_THREADS;
    int lsense = 0;

    // ---- A: histogram (g_cnt is pre-zeroed) + fp16 feature conversion ----
    for (int e = gtid; e < E; e += gthreads)
        atomicAdd(&g_cnt[rel_idx[e]], 1);
    {
        const float4* f4 = reinterpret_cast<const float4*>(feat);
        int total = N * 32;
        for (int i = gtid; i < total; i += gthreads) {
            float4 v = f4[i];
            __half2 a = __floats2half2_rn(v.x, v.y);
            __half2 c = __floats2half2_rn(v.z, v.w);
            uint2 o;
            o.x = *reinterpret_cast<uint32_t*>(&a);
            o.y = *reinterpret_cast<uint32_t*>(&c);
            g_feat16[i] = o;
        }
    }
    gbar(grid, &lsense);   // 1

    // ---- B: per-chunk (1024) exclusive scan + chunk totals ----
    for (int c = cta; c < nchunks; c += grid) {
        int i = c * MEGA_THREADS + tid;
        int v = (i < N) ? g_cnt[i] : 0;
        int x = v;
        #pragma unroll
        for (int o = 1; o < 32; o <<= 1) {
            int y = __shfl_up_sync(0xffffffffu, x, o);
            if ((tid & 31) >= o) x += y;
        }
        if ((tid & 31) == 31) ws[tid >> 5] = x;
        __syncthreads();
        if (tid < 32) {
            int w = ws[tid];
            int xx = w;
            #pragma unroll
            for (int o = 1; o < 32; o <<= 1) {
                int y = __shfl_up_sync(0xffffffffu, xx, o);
                if (tid >= o) xx += y;
            }
            ws[tid] = xx - w;
        }
        __syncthreads();
        int excl = (x - v) + ws[tid >> 5];
        if (i < N) g_rowstart[i] = excl;
        if (tid == MEGA_THREADS - 1) g_chunksum[c] = excl + v;
        __syncthreads();
    }
    gbar(grid, &lsense);   // 2

    // ---- C: redundant chunk-total scan (per CTA) + offsets + cursor ----
    {
        int v = (tid < nchunks) ? g_chunksum[tid] : 0;
        int x = v;
        #pragma unroll
        for (int o = 1; o < 32; o <<= 1) {
            int y = __shfl_up_sync(0xffffffffu, x, o);
            if ((tid & 31) >= o) x += y;
        }
        if ((tid & 31) == 31) ws[tid >> 5] = x;
        __syncthreads();
        if (tid < 32) {
            int w = ws[tid];
            int xx = w;
            #pragma unroll
            for (int o = 1; o < 32; o <<= 1) {
                int y = __shfl_up_sync(0xffffffffu, xx, o);
                if (tid >= o) xx += y;
            }
            ws[tid] = xx - w;
        }
        __syncthreads();
        int excl = (x - v) + ws[tid >> 5];
        if (tid < nchunks) chunkoff[tid] = excl;
        __syncthreads();

        for (int i = gtid; i < N; i += gthreads) {
            int v2 = g_rowstart[i] + chunkoff[i >> 10];
            g_rowstart[i] = v2;
            g_cursor[i]   = v2;
        }
        if (gtid == 0) g_rowstart[N] = E;
    }
    gbar(grid, &lsense);   // 3

    // ---- D: scatter edges + re-zero cnt for next call ----
    for (int e = gtid; e < E; e += gthreads) {
        int dst = rel_idx[e];
        int src = rel_idx[E + e];
        float w = rw[e];
        int p = atomicAdd(&g_cursor[dst], 1);
        g_edges[p] = make_int2(src, __float_as_int(w));
    }
    for (int i = gtid; i < N; i += gthreads) g_cnt[i] = 0;
    gbar(grid, &lsense);   // 4 (even -> sense back to 0 for replay)

    // ---- E: warp-per-node aggregation, 4 edges in flight per half-warp ----
    {
        const uint4* feat4 = reinterpret_cast<const uint4*>(g_feat16);
        int gwarps = gthreads >> 5;
        int lane = tid & 31;
        int half = lane >> 4;
        int hl   = lane & 15;
        for (int node = gtid >> 5; node < N; node += gwarps) {
            int beg = g_rowstart[node];
            int end = g_rowstart[node + 1];

            float a[8] = {0.f,0.f,0.f,0.f,0.f,0.f,0.f,0.f};
            int i = beg + half;
            #pragma unroll 1
            for (; i + 6 < end; i += 8) {
                int2 eA = g_edges[i];
                int2 eB = g_edges[i + 2];
                int2 eC = g_edges[i + 4];
                int2 eD = g_edges[i + 6];
                uint4 uA = feat4[(size_t)eA.x * 16 + hl];
                uint4 uB = feat4[(size_t)eB.x * 16 + hl];
                uint4 uC = feat4[(size_t)eC.x * 16 + hl];
                uint4 uD = feat4[(size_t)eD.x * 16 + hl];
                agg_edge(a, uA, __int_as_float(eA.y));
                agg_edge(a, uB, __int_as_float(eB.y));
                agg_edge(a, uC, __int_as_float(eC.y));
                agg_edge(a, uD, __int_as_float(eD.y));
            }
            #pragma unroll 1
            for (; i < end; i += 2) {
                int2 eA = g_edges[i];
                uint4 uA = feat4[(size_t)eA.x * 16 + hl];
                agg_edge(a, uA, __int_as_float(eA.y));
            }

            #pragma unroll
            for (int q = 0; q < 8; q++)
                a[q] += __shfl_xor_sync(0xffffffffu, a[q], 16);

            if (half == 0) {
                int deg = end - beg;
                float inv = 1.0f / (float)(deg > 1 ? deg : 1);
                __half2 m0 = __floats2half2_rn(a[0] * inv, a[1] * inv);
                __half2 m1 = __floats2half2_rn(a[2] * inv, a[3] * inv);
                __half2 m2 = __floats2half2_rn(a[4] * inv, a[5] * inv);
                __half2 m3 = __floats2half2_rn(a[6] * inv, a[7] * inv);
                uint4 o;
                o.x = *reinterpret_cast<uint32_t*>(&m0);
                o.y = *reinterpret_cast<uint32_t*>(&m1);
                o.z = *reinterpret_cast<uint32_t*>(&m2);
                o.w = *reinterpret_cast<uint32_t*>(&m3);
                reinterpret_cast<uint4*>(g_mean16)[(size_t)node * 16 + hl] = o;
            }
        }
    }
}

// ---------------------------------------------------------------------------
// GEMM: flat cross-strip pipeline. Warp-private 32-row strips; chunks of
// 2 k-steps in 3 rotating buffers (stride 20 words, ldmatrix conflict-free);
// issue cursor runs 3 chunks ahead of compute, across strip boundaries.
// W col-half per CTA. No main-loop __syncthreads. 2 CTAs/SM.
// ---------------------------------------------------------------------------
#define GEMM_THREADS 256
#define WS_STRIDE 132                          // uint32 per n-row (W half)
#define WH_WORDS (64 * WS_STRIDE)              // 8448
#define AC_STRIDE 20                           // uint32 per m-row per chunk
#define AW_CHUNK (32 * AC_STRIDE)              // 640 words per warp chunk
#define NBUF 3
#define GEMM_SMEM ((WH_WORDS + 8 * NBUF * AW_CHUNK) * 4)   // 95232 B

__device__ __forceinline__ uint32_t smem_u32(const void* p) {
    uint32_t a;
    asm("{ .reg .u64 t; cvta.to.shared.u64 t, %1; cvt.u32.u64 %0, t; }"
        : "=r"(a) : "l"(p));
    return a;
}

__device__ __forceinline__ void cp_async16(uint32_t dst, const void* src,
                                           uint32_t zfill) {
    asm volatile("cp.async.cg.shared.global [%0], [%1], 16, %2;"
                 :: "r"(dst), "l"(src), "r"(zfill) : "memory");
}

__device__ __forceinline__ void mma_fp16(float& c0, float& c1, float& c2, float& c3,
                                         uint32_t a0, uint32_t a1, uint32_t a2, uint32_t a3,
                                         uint32_t b0, uint32_t b1) {
    asm volatile(
        "mma.sync.aligned.m16n8k16.row.col.f32.f16.f16.f32 "
        "{%0,%1,%2,%3}, {%4,%5,%6,%7}, {%8,%9}, {%0,%1,%2,%3};"
        : "+f"(c0), "+f"(c1), "+f"(c2), "+f"(c3)
        : "r"(a0), "r"(a1), "r"(a2), "r"(a3), "r"(b0), "r"(b1));
}

__global__ void __launch_bounds__(GEMM_THREADS, 2) gemm_kernel(
    const float* __restrict__ W,
    const float* __restrict__ b,
    float*       __restrict__ out,
    int N, int n_strips)
{
    extern __shared__ uint32_t smem[];
    uint32_t* Ws = smem;                       // [64 n][WS_STRIDE]
    uint32_t* Ab = smem + WH_WORDS;            // 8 warps x NBUF x AW_CHUNK

    const int tid  = threadIdx.x;
    const int wid  = tid >> 5;
    const int lane = tid & 31;
    const int gid  = lane >> 2;
    const int tig  = lane & 3;
    const int ch   = blockIdx.x & 1;           // column half (grid is even)

    // --- stage W col-half once ---
    for (int idx = tid; idx < 64 * 128; idx += GEMM_THREADS) {
        int n  = idx & 63;
        int kp = idx >> 6;
        __half2 h = __floats2half2_rn(W[(2 * kp) * OUT_DIM + ch * 64 + n],
                                      W[(2 * kp + 1) * OUT_DIM + ch * 64 + n]);
        Ws[n * WS_STRIDE + kp] = *reinterpret_cast<uint32_t*>(&h);
    }
    __syncthreads();   // only block-wide sync in the kernel

    const uint32_t lmB = smem_u32(Ws)
        + (((lane & 7) + ((lane >> 4) & 1) * 8) * WS_STRIDE
           + ((lane >> 3) & 1) * 4) * 4;
    const uint32_t abw = smem_u32(Ab) + (uint32_t)(wid * NBUF * AW_CHUNK) * 4;
    const uint32_t lmA_off =
        ((((lane >> 3) & 1) * 8 + (lane & 7)) * AC_STRIDE
         + ((lane >> 4) & 1) * 4) * 4;

    const int cp_r = lane >> 2;                // 0..7 (row within 8)
    const int cp_q = lane & 3;                 // 0..3 (uint4 within chunk row)

    const uint4* feat4 = reinterpret_cast<const uint4*>(g_feat16);
    const uint4* mean4 = reinterpret_cast<const uint4*>(g_mean16);

    const int warp_g  = (blockIdx.x >> 1) * 8 + wid;
    const int wstride = (gridDim.x >> 1) * 8;

    // --- flat issue cursor (strip_i, chunk_i) -> buffer buf_i ---
    int strip_i = warp_g;
    int chunk_i = 0;
    int buf_i   = 0;

    auto issue_one = [&]() {
        if (strip_i < n_strips) {
            const uint4* table = (chunk_i < 4) ? feat4 : mean4;
            const int qoff = (chunk_i & 3) * 4;
            const int node0 = strip_i * 32;
            #pragma unroll
            for (int i = 0; i < 4; i++) {
                int row  = cp_r + i * 8;
                int node = node0 + row;
                bool v = node < N;
                const uint4* src = &table[(size_t)(v ? node : 0) * 16 + qoff + cp_q];
                uint32_t dst = abw + (uint32_t)(buf_i * AW_CHUNK
                              + row * AC_STRIDE + cp_q * 4) * 4;
                cp_async16(dst, src, v ? 16u : 0u);
            }
        }
        asm volatile("cp.async.commit_group;" ::: "memory");
        if (++chunk_i == 8) { chunk_i = 0; strip_i += wstride; }
        if (++buf_i == NBUF) buf_i = 0;
    };

    issue_one(); issue_one(); issue_one();     // pipeline fill (3 deep)

    int buf_c = 0;
    for (int strip = warp_g; strip < n_strips; strip += wstride) {
        const int node0 = strip * 32;

        float acc[2][8][4];
        #pragma unroll
        for (int m = 0; m < 2; m++)
            #pragma unroll
            for (int nt = 0; nt < 8; nt++)
                #pragma unroll
                for (int q = 0; q < 4; q++) acc[m][nt][q] = 0.f;

        #pragma unroll
        for (int c = 0; c < 8; c++) {
            asm volatile("cp.async.wait_group %0;" :: "n"(NBUF - 1) : "memory");
            const uint32_t lmAc = abw + (uint32_t)(buf_c * AW_CHUNK) * 4 + lmA_off;
            #pragma unroll
            for (int s2 = 0; s2 < 2; s2++) {
                const int step = c * 2 + s2;
                uint32_t a[2][4];
                #pragma unroll
                for (int m = 0; m < 2; m++) {
                    asm volatile(
                        "ldmatrix.sync.aligned.m8n8.x4.shared.b16 {%0,%1,%2,%3}, [%4];"
                        : "=r"(a[m][0]), "=r"(a[m][1]), "=r"(a[m][2]), "=r"(a[m][3])
                        : "r"(lmAc + (uint32_t)(m * 16 * AC_STRIDE * 4 + s2 * 32)));
                }
                const uint32_t kb = (uint32_t)(step * 32);
                #pragma unroll
                for (int p = 0; p < 4; p++) {
                    uint32_t b0, b1, b2, b3;
                    asm volatile(
                        "ldmatrix.sync.aligned.m8n8.x4.shared.b16 {%0,%1,%2,%3}, [%4];"
                        : "=r"(b0), "=r"(b1), "=r"(b2), "=r"(b3)
                        : "r"(lmB + (uint32_t)(p * 16 * WS_STRIDE * 4) + kb));
                    #pragma unroll
                    for (int m = 0; m < 2; m++) {
                        mma_fp16(acc[m][2*p][0], acc[m][2*p][1],
                                 acc[m][2*p][2], acc[m][2*p][3],
                                 a[m][0], a[m][1], a[m][2], a[m][3], b0, b1);
                        mma_fp16(acc[m][2*p+1][0], acc[m][2*p+1][1],
                                 acc[m][2*p+1][2], acc[m][2*p+1][3],
                                 a[m][0], a[m][1], a[m][2], a[m][3], b2, b3);
                    }
                }
            }
            if (++buf_c == NBUF) buf_c = 0;
            issue_one();                        // refill (crosses strips)
        }

        // --- epilogue: bias + float2 stores (next chunks already in flight) ---
        #pragma unroll
        for (int m = 0; m < 2; m++) {
            int row0 = node0 + m * 16 + gid;
            int row1 = row0 + 8;
            #pragma unroll
            for (int nt = 0; nt < 8; nt++) {
                int col = ch * 64 + nt * 8 + tig * 2;
                float2 bi2 = *reinterpret_cast<const float2*>(&b[col]);
                if (row0 < N) {
                    float2 oo = make_float2(acc[m][nt][0] + bi2.x,
                                            acc[m][nt][1] + bi2.y);
                    *reinterpret_cast<float2*>(&out[(size_t)row0 * OUT_DIM + col]) = oo;
                }
                if (row1 < N) {
                    float2 oo = make_float2(acc[m][nt][2] + bi2.x,
                                            acc[m][nt][3] + bi2.y);
                    *reinterpret_cast<float2*>(&out[(size_t)row1 * OUT_DIM + col]) = oo;
                }
            }
        }
    }
}

// ---------------------------------------------------------------------------
// Launch
// ---------------------------------------------------------------------------
extern "C" void kernel_launch(void* const* d_in, const int* in_sizes, int n_in,
                              void* d_out, int out_size)
{
    const float* feat    = (const float*)d_in[0];
    const float* rw      = (const float*)d_in[1];
    const float* W       = (const float*)d_in[2];
    const float* b       = (const float*)d_in[3];
    const int*   rel_idx = (const int*)d_in[4];

    const int N = in_sizes[0] / D_FEAT;
    const int E = in_sizes[1];
    float* out = (float*)d_out;

    int sm = 0;
    if (cudaDeviceGetAttribute(&sm, cudaDevAttrMultiProcessorCount, 0)
        != cudaSuccess || sm <= 0) sm = 148;

    mega_kernel<<<sm, MEGA_THREADS>>>(feat, rw, rel_idx, N, E, sm);

    int n_strips = (N + 31) / 32;
    int grid = 2 * sm;                 // even: blockIdx parity = column half
    cudaFuncSetAttribute(gemm_kernel,
                         cudaFuncAttributeMaxDynamicSharedMemorySize, GEMM_SMEM);
    gemm_kernel<<<grid, GEMM_THREADS, GEMM_SMEM>>>(W, b, out, N, n_strips);
}

// round 17
// speedup vs baseline: 1.0580x; 1.0580x over previous
#include <cuda_runtime.h>
#include <cuda_bf16.h>
#include <cuda_fp16.h>
#include <cstdint>

// ---------------------------------------------------------------------------
// SAGESparseLayer:
//   mean[n] = (1/max(deg(n),1)) * sum_{e: dst[e]==n} feature[src[e]] * rw[e]
//   out[n]  = [feature[n], mean[n]] @ W + b
//
// R17: launches = [mega, gemm].
//  mega (4 gbars): A hist+convert | B chunk scan | C offsets | D scatter+zero
//   | E flat edge-stream aggregation (half-warp per balanced edge range,
//     4-edge load pipeline regardless of node degree).
//  gemm: R14 version (warp-private 32-row strips, cp.async double buffer,
//        W col-half per CTA, 2 CTAs/SM).
// ---------------------------------------------------------------------------

#define D_FEAT    128
#define OUT_DIM   128
#define MAX_NODES 131072
#define MAX_EDGES (1 << 20)
#define MAX_CHUNKS 256
#define MEGA_THREADS 1024

static __device__ __align__(16) uint2 g_feat16[(size_t)MAX_NODES * 32];  // fp16 feat
static __device__ __align__(16) uint2 g_mean16[(size_t)MAX_NODES * 32];  // fp16 mean
static __device__ int  g_cnt[MAX_NODES];          // ZERO at every launch entry
static __device__ int  g_rowstart[MAX_NODES + 1];
static __device__ int  g_cursor[MAX_NODES];
static __device__ int  g_chunksum[MAX_CHUNKS];
static __device__ __align__(8) int2 g_edges[MAX_EDGES];

// software grid barrier state (replay-safe: even #barriers per launch)
static __device__ int g_bar_cnt;
static __device__ volatile int g_bar_sense;

__device__ __forceinline__ void gbar(int grid, int* lsense) {
    __syncthreads();
    if (threadIdx.x == 0) {
        int s = *lsense ^ 1;
        *lsense = s;
        __threadfence();
        if (atomicAdd(&g_bar_cnt, 1) == grid - 1) {
            g_bar_cnt = 0;
            __threadfence();
            g_bar_sense = s;
        } else {
            while (g_bar_sense != s) __nanosleep(64);
        }
        __threadfence();
    }
    __syncthreads();
}

// ---------------------------------------------------------------------------
// agg helper: accumulate one edge's 8 features (fp16x2 -> f32 fma)
// ---------------------------------------------------------------------------
__device__ __forceinline__ void agg_edge(float* a, uint4 u, float w) {
    float2 p;
    p = __half22float2(*reinterpret_cast<__half2*>(&u.x));
    a[0] = fmaf(p.x, w, a[0]); a[1] = fmaf(p.y, w, a[1]);
    p = __half22float2(*reinterpret_cast<__half2*>(&u.y));
    a[2] = fmaf(p.x, w, a[2]); a[3] = fmaf(p.y, w, a[3]);
    p = __half22float2(*reinterpret_cast<__half2*>(&u.z));
    a[4] = fmaf(p.x, w, a[4]); a[5] = fmaf(p.y, w, a[5]);
    p = __half22float2(*reinterpret_cast<__half2*>(&u.w));
    a[6] = fmaf(p.x, w, a[6]); a[7] = fmaf(p.y, w, a[7]);
}

// ---------------------------------------------------------------------------
// mega kernel
// ---------------------------------------------------------------------------
__global__ void __launch_bounds__(MEGA_THREADS, 1) mega_kernel(
    const float* __restrict__ feat,
    const float* __restrict__ rw,
    const int*   __restrict__ rel_idx,
    int N, int E, int grid)
{
    __shared__ int ws[32];
    __shared__ int chunkoff[MAX_CHUNKS];
    const int tid = threadIdx.x;
    const int cta = blockIdx.x;
    const int gthreads = grid * MEGA_THREADS;
    const int gtid = cta * MEGA_THREADS + tid;
    const int nchunks = (N + MEGA_THREADS - 1) / MEGA_THREADS;
    int lsense = 0;

    // ---- A: histogram (g_cnt is pre-zeroed) + fp16 feature conversion ----
    for (int e = gtid; e < E; e += gthreads)
        atomicAdd(&g_cnt[rel_idx[e]], 1);
    {
        const float4* f4 = reinterpret_cast<const float4*>(feat);
        int total = N * 32;
        for (int i = gtid; i < total; i += gthreads) {
            float4 v = f4[i];
            __half2 a = __floats2half2_rn(v.x, v.y);
            __half2 c = __floats2half2_rn(v.z, v.w);
            uint2 o;
            o.x = *reinterpret_cast<uint32_t*>(&a);
            o.y = *reinterpret_cast<uint32_t*>(&c);
            g_feat16[i] = o;
        }
    }
    gbar(grid, &lsense);   // 1

    // ---- B: per-chunk (1024) exclusive scan + chunk totals ----
    for (int c = cta; c < nchunks; c += grid) {
        int i = c * MEGA_THREADS + tid;
        int v = (i < N) ? g_cnt[i] : 0;
        int x = v;
        #pragma unroll
        for (int o = 1; o < 32; o <<= 1) {
            int y = __shfl_up_sync(0xffffffffu, x, o);
            if ((tid & 31) >= o) x += y;
        }
        if ((tid & 31) == 31) ws[tid >> 5] = x;
        __syncthreads();
        if (tid < 32) {
            int w = ws[tid];
            int xx = w;
            #pragma unroll
            for (int o = 1; o < 32; o <<= 1) {
                int y = __shfl_up_sync(0xffffffffu, xx, o);
                if (tid >= o) xx += y;
            }
            ws[tid] = xx - w;
        }
        __syncthreads();
        int excl = (x - v) + ws[tid >> 5];
        if (i < N) g_rowstart[i] = excl;
        if (tid == MEGA_THREADS - 1) g_chunksum[c] = excl + v;
        __syncthreads();
    }
    gbar(grid, &lsense);   // 2

    // ---- C: redundant chunk-total scan (per CTA) + offsets + cursor ----
    {
        int v = (tid < nchunks) ? g_chunksum[tid] : 0;
        int x = v;
        #pragma unroll
        for (int o = 1; o < 32; o <<= 1) {
            int y = __shfl_up_sync(0xffffffffu, x, o);
            if ((tid & 31) >= o) x += y;
        }
        if ((tid & 31) == 31) ws[tid >> 5] = x;
        __syncthreads();
        if (tid < 32) {
            int w = ws[tid];
            int xx = w;
            #pragma unroll
            for (int o = 1; o < 32; o <<= 1) {
                int y = __shfl_up_sync(0xffffffffu, xx, o);
                if (tid >= o) xx += y;
            }
            ws[tid] = xx - w;
        }
        __syncthreads();
        int excl = (x - v) + ws[tid >> 5];
        if (tid < nchunks) chunkoff[tid] = excl;
        __syncthreads();

        for (int i = gtid; i < N; i += gthreads) {
            int v2 = g_rowstart[i] + chunkoff[i >> 10];
            g_rowstart[i] = v2;
            g_cursor[i]   = v2;
        }
        if (gtid == 0) g_rowstart[N] = E;
    }
    gbar(grid, &lsense);   // 3

    // ---- D: scatter edges + re-zero cnt for next call ----
    for (int e = gtid; e < E; e += gthreads) {
        int dst = rel_idx[e];
        int src = rel_idx[E + e];
        float w = rw[e];
        int p = atomicAdd(&g_cursor[dst], 1);
        g_edges[p] = make_int2(src, __float_as_int(w));
    }
    for (int i = gtid; i < N; i += gthreads) g_cnt[i] = 0;
    gbar(grid, &lsense);   // 4 (even -> sense back to 0 for replay)

    // ---- E: flat edge-stream aggregation ----
    // Half-warp per balanced edge range (complete nodes). 4-edge load
    // pipeline regardless of node degree; flush accumulator at boundaries.
    // Note: zero-degree tail nodes with rowstart == E are never flushed by
    // any half-warp; their correct mean is 0 and g_mean16 is never written
    // for them (stays at zero-init), which is correct.
    {
        const uint4* feat4 = reinterpret_cast<const uint4*>(g_feat16);
        const int ghw = gthreads >> 4;       // global half-warp count
        const int hw  = gtid >> 4;
        const int hl  = tid & 15;

        const int s0 = (int)((long long)hw * E / ghw);
        const int s1 = (int)((long long)(hw + 1) * E / ghw);

        // lower_bound: first n in [0,N] with rowstart[n] >= target
        auto lb = [&](int target) {
            int lo = 0, hi = N;
            while (lo < hi) {
                int mid = (lo + hi) >> 1;
                if (g_rowstart[mid] < target) lo = mid + 1; else hi = mid;
            }
            return lo;
        };
        int n_begin = lb(s0);
        int n_end   = lb(s1);

        if (n_begin < n_end) {
            int n  = n_begin;
            int cs = g_rowstart[n];          // current node's start
            int nb = g_rowstart[n + 1];      // current node's end (boundary)
            int e  = cs;
            const int e_last = g_rowstart[n_end];

            float a[8] = {0.f,0.f,0.f,0.f,0.f,0.f,0.f,0.f};

            auto flush = [&]() {
                int deg = nb - cs;
                float inv = 1.0f / (float)(deg > 1 ? deg : 1);
                __half2 m0 = __floats2half2_rn(a[0] * inv, a[1] * inv);
                __half2 m1 = __floats2half2_rn(a[2] * inv, a[3] * inv);
                __half2 m2 = __floats2half2_rn(a[4] * inv, a[5] * inv);
                __half2 m3 = __floats2half2_rn(a[6] * inv, a[7] * inv);
                uint4 o;
                o.x = *reinterpret_cast<uint32_t*>(&m0);
                o.y = *reinterpret_cast<uint32_t*>(&m1);
                o.z = *reinterpret_cast<uint32_t*>(&m2);
                o.w = *reinterpret_cast<uint32_t*>(&m3);
                reinterpret_cast<uint4*>(g_mean16)[(size_t)n * 16 + hl] = o;
                #pragma unroll
                for (int q = 0; q < 8; q++) a[q] = 0.f;
                cs = nb;
                n++;
                nb = g_rowstart[n + 1];
            };

            while (e < e_last) {
                int m = e_last - e;
                if (m > 4) m = 4;
                int2  ed[4];
                uint4 u[4];
                #pragma unroll
                for (int j = 0; j < 4; j++)
                    if (j < m) ed[j] = g_edges[e + j];
                #pragma unroll
                for (int j = 0; j < 4; j++)
                    if (j < m) u[j] = feat4[(size_t)ed[j].x * 16 + hl];
                #pragma unroll
                for (int j = 0; j < 4; j++) {
                    if (j < m) {
                        while (e + j == nb) flush();   // node(s) complete
                        agg_edge(a, u[j], __int_as_float(ed[j].y));
                    }
                }
                e += m;
            }
            // trailing flushes (incl. zero-degree nodes in range)
            while (n < n_end) flush();
        }
    }
}

// ---------------------------------------------------------------------------
// GEMM (R14 version): warp-private 32-row strips, col-half W per CTA,
// cp.async double buffer per warp, no main-loop __syncthreads. 2 CTAs/SM.
// ---------------------------------------------------------------------------
#define GEMM_THREADS 256
#define WS_STRIDE 132                          // uint32 per n-row (W half)
#define WH_WORDS (64 * WS_STRIDE)              // 8448
#define AC_STRIDE 36                           // uint32 per m-row per chunk
#define AW_CHUNK (32 * AC_STRIDE)              // 1152 words per warp chunk
#define GEMM_SMEM ((WH_WORDS + 8 * 2 * AW_CHUNK) * 4)   // 107520 B

__device__ __forceinline__ uint32_t smem_u32(const void* p) {
    uint32_t a;
    asm("{ .reg .u64 t; cvta.to.shared.u64 t, %1; cvt.u32.u64 %0, t; }"
        : "=r"(a) : "l"(p));
    return a;
}

__device__ __forceinline__ void cp_async16(uint32_t dst, const void* src,
                                           uint32_t zfill) {
    asm volatile("cp.async.cg.shared.global [%0], [%1], 16, %2;"
                 :: "r"(dst), "l"(src), "r"(zfill) : "memory");
}

__device__ __forceinline__ void mma_fp16(float& c0, float& c1, float& c2, float& c3,
                                         uint32_t a0, uint32_t a1, uint32_t a2, uint32_t a3,
                                         uint32_t b0, uint32_t b1) {
    asm volatile(
        "mma.sync.aligned.m16n8k16.row.col.f32.f16.f16.f32 "
        "{%0,%1,%2,%3}, {%4,%5,%6,%7}, {%8,%9}, {%0,%1,%2,%3};"
        : "+f"(c0), "+f"(c1), "+f"(c2), "+f"(c3)
        : "r"(a0), "r"(a1), "r"(a2), "r"(a3), "r"(b0), "r"(b1));
}

__global__ void __launch_bounds__(GEMM_THREADS, 2) gemm_kernel(
    const float* __restrict__ W,
    const float* __restrict__ b,
    float*       __restrict__ out,
    int N, int n_strips)
{
    extern __shared__ uint32_t smem[];
    uint32_t* Ws = smem;                       // [64 n][WS_STRIDE]
    uint32_t* Ab = smem + WH_WORDS;            // 8 warps x 2 x AW_CHUNK

    const int tid  = threadIdx.x;
    const int wid  = tid >> 5;
    const int lane = tid & 31;
    const int gid  = lane >> 2;
    const int tig  = lane & 3;
    const int ch   = blockIdx.x & 1;           // column half (grid is even)

    // --- stage W col-half once ---
    for (int idx = tid; idx < 64 * 128; idx += GEMM_THREADS) {
        int n  = idx & 63;
        int kp = idx >> 6;
        __half2 h = __floats2half2_rn(W[(2 * kp) * OUT_DIM + ch * 64 + n],
                                      W[(2 * kp + 1) * OUT_DIM + ch * 64 + n]);
        Ws[n * WS_STRIDE + kp] = *reinterpret_cast<uint32_t*>(&h);
    }
    __syncthreads();   // only block-wide sync in the kernel

    const uint32_t lmB = smem_u32(Ws)
        + (((lane & 7) + ((lane >> 4) & 1) * 8) * WS_STRIDE
           + ((lane >> 3) & 1) * 4) * 4;
    const uint32_t abw = smem_u32(Ab) + (uint32_t)(wid * 2 * AW_CHUNK) * 4;
    const uint32_t lmA_off =
        ((((lane >> 3) & 1) * 8 + (lane & 7)) * AC_STRIDE
         + ((lane >> 4) & 1) * 4) * 4;

    const int cp_r = lane >> 3;                // 0..3
    const int cp_q = lane & 7;                 // 0..7

    const uint4* feat4 = reinterpret_cast<const uint4*>(g_feat16);
    const uint4* mean4 = reinterpret_cast<const uint4*>(g_mean16);

    const int warp_g  = (blockIdx.x >> 1) * 8 + wid;
    const int wstride = (gridDim.x >> 1) * 8;

    for (int strip = warp_g; strip < n_strips; strip += wstride) {
        const int node0 = strip * 32;

        auto issue = [&](int c, int p) {
            const uint4* table = (c < 2) ? feat4 : mean4;
            int qoff = (c & 1) * 8;
            #pragma unroll
            for (int i = 0; i < 8; i++) {
                int row  = i * 4 + cp_r;
                int node = node0 + row;
                bool v = node < N;
                const uint4* src = &table[(size_t)(v ? node : 0) * 16 + qoff + cp_q];
                uint32_t dst = abw + (uint32_t)(p * AW_CHUNK
                              + row * AC_STRIDE + cp_q * 4) * 4;
                cp_async16(dst, src, v ? 16u : 0u);
            }
            asm volatile("cp.async.commit_group;" ::: "memory");
        };

        float acc[2][8][4];
        #pragma unroll
        for (int m = 0; m < 2; m++)
            #pragma unroll
            for (int nt = 0; nt < 8; nt++)
                #pragma unroll
                for (int q = 0; q < 4; q++) acc[m][nt][q] = 0.f;

        issue(0, 0);
        issue(1, 1);

        #pragma unroll
        for (int c = 0; c < 4; c++) {
            if (c < 3) {
                asm volatile("cp.async.wait_group 1;" ::: "memory");
            } else {
                asm volatile("cp.async.wait_group 0;" ::: "memory");
            }
            const uint32_t lmAc = abw + (uint32_t)((c & 1) * AW_CHUNK) * 4 + lmA_off;
            #pragma unroll
            for (int s2 = 0; s2 < 4; s2++) {
                const int step = c * 4 + s2;
                uint32_t a[2][4];
                #pragma unroll
                for (int m = 0; m < 2; m++) {
                    asm volatile(
                        "ldmatrix.sync.aligned.m8n8.x4.shared.b16 {%0,%1,%2,%3}, [%4];"
                        : "=r"(a[m][0]), "=r"(a[m][1]), "=r"(a[m][2]), "=r"(a[m][3])
                        : "r"(lmAc + (uint32_t)(m * 16 * AC_STRIDE * 4 + s2 * 32)));
                }
                const uint32_t kb = (uint32_t)(step * 32);
                #pragma unroll
                for (int p = 0; p < 4; p++) {
                    uint32_t b0, b1, b2, b3;
                    asm volatile(
                        "ldmatrix.sync.aligned.m8n8.x4.shared.b16 {%0,%1,%2,%3}, [%4];"
                        : "=r"(b0), "=r"(b1), "=r"(b2), "=r"(b3)
                        : "r"(lmB + (uint32_t)(p * 16 * WS_STRIDE * 4) + kb));
                    #pragma unroll
                    for (int m = 0; m < 2; m++) {
                        mma_fp16(acc[m][2*p][0], acc[m][2*p][1],
                                 acc[m][2*p][2], acc[m][2*p][3],
                                 a[m][0], a[m][1], a[m][2], a[m][3], b0, b1);
                        mma_fp16(acc[m][2*p+1][0], acc[m][2*p+1][1],
                                 acc[m][2*p+1][2], acc[m][2*p+1][3],
                                 a[m][0], a[m][1], a[m][2], a[m][3], b2, b3);
                    }
                }
            }
            if (c < 2) issue(c + 2, c & 1);   // warp-private buffer: no sync
        }

        // --- epilogue: bias + float2 stores ---
        #pragma unroll
        for (int m = 0; m < 2; m++) {
            int row0 = node0 + m * 16 + gid;
            int row1 = row0 + 8;
            #pragma unroll
            for (int nt = 0; nt < 8; nt++) {
                int col = ch * 64 + nt * 8 + tig * 2;
                float2 bi2 = *reinterpret_cast<const float2*>(&b[col]);
                if (row0 < N) {
                    float2 oo = make_float2(acc[m][nt][0] + bi2.x,
                                            acc[m][nt][1] + bi2.y);
                    *reinterpret_cast<float2*>(&out[(size_t)row0 * OUT_DIM + col]) = oo;
                }
                if (row1 < N) {
                    float2 oo = make_float2(acc[m][nt][2] + bi2.x,
                                            acc[m][nt][3] + bi2.y);
                    *reinterpret_cast<float2*>(&out[(size_t)row1 * OUT_DIM + col]) = oo;
                }
            }
        }
    }
}

// ---------------------------------------------------------------------------
// Launch
// ---------------------------------------------------------------------------
extern "C" void kernel_launch(void* const* d_in, const int* in_sizes, int n_in,
                              void* d_out, int out_size)
{
    const float* feat    = (const float*)d_in[0];
    const float* rw      = (const float*)d_in[1];
    const float* W       = (const float*)d_in[2];
    const float* b       = (const float*)d_in[3];
    const int*   rel_idx = (const int*)d_in[4];

    const int N = in_sizes[0] / D_FEAT;
    const int E = in_sizes[1];
    float* out = (float*)d_out;

    int sm = 0;
    if (cudaDeviceGetAttribute(&sm, cudaDevAttrMultiProcessorCount, 0)
        != cudaSuccess || sm <= 0) sm = 148;

    mega_kernel<<<sm, MEGA_THREADS>>>(feat, rw, rel_idx, N, E, sm);

    int n_strips = (N + 31) / 32;
    int grid = 2 * sm;                 // even: blockIdx parity = column half
    cudaFuncSetAttribute(gemm_kernel,
                         cudaFuncAttributeMaxDynamicSharedMemorySize, GEMM_SMEM);
    gemm_kernel<<<grid, GEMM_THREADS, GEMM_SMEM>>>(W, b, out, N, n_strips);
}